// round 3
// baseline (speedup 1.0000x reference)
#include <cuda_runtime.h>
#include <math.h>

#define BDIM 8
#define NDIM 4096
#define DDIM 768
#define HDIM 256
#define NCHUNK 64
#define ROWS_PER_CHUNK (NDIM / NCHUNK)

// ---- scratch (no cudaMalloc allowed) ----
__device__ float g_partial[BDIM * NCHUNK * DDIM];
__device__ float g_c[BDIM * DDIM];
__device__ float g_delta[BDIM * DDIM];

// =====================================================================
// Kernel 1a: partial sums over N-chunks.  grid (NCHUNK, B), block DDIM
// =====================================================================
__global__ void k_mean_part(const float* __restrict__ x) {
    int chunk = blockIdx.x;
    int b = blockIdx.y;
    int d = threadIdx.x;
    const float* p = x + ((size_t)b * NDIM + (size_t)chunk * ROWS_PER_CHUNK) * DDIM + d;
    float acc = 0.f;
#pragma unroll 8
    for (int i = 0; i < ROWS_PER_CHUNK; i++) acc += p[(size_t)i * DDIM];
    g_partial[(b * NCHUNK + chunk) * DDIM + d] = acc;
}

// =====================================================================
// Kernel 1b: final mean.  grid B, block DDIM
// =====================================================================
__global__ void k_mean_fin() {
    int b = blockIdx.x;
    int d = threadIdx.x;
    float acc = 0.f;
#pragma unroll 8
    for (int ch = 0; ch < NCHUNK; ch++) acc += g_partial[(b * NCHUNK + ch) * DDIM + d];
    g_c[b * DDIM + d] = acc * (1.0f / NDIM);
}

// =====================================================================
// Kernel 2: fused MLP per batch.  grid B, block DDIM (768)
// =====================================================================
__global__ void k_mlp(const float* __restrict__ w1, const float* __restrict__ b1,
                      const float* __restrict__ w2, const float* __restrict__ b2) {
    __shared__ float cs[DDIM];
    __shared__ float hs[HDIM];
    int b = blockIdx.x;
    int t = threadIdx.x;
    cs[t] = g_c[b * DDIM + t];
    __syncthreads();
    if (t < HDIM) {
        float acc = b1[t];
#pragma unroll 8
        for (int k = 0; k < DDIM; k++) acc = fmaf(cs[k], w1[k * HDIM + t], acc);
        float x3 = acc * acc * acc;
        float g = 0.5f * acc * (1.0f + tanhf(0.7978845608028654f * (acc + 0.044715f * x3)));
        hs[t] = g;
    }
    __syncthreads();
    float acc = b2[t];
#pragma unroll 8
    for (int k = 0; k < HDIM; k++) acc = fmaf(hs[k], w2[k * DDIM + t], acc);
    g_delta[b * DDIM + t] = acc;
}

// =====================================================================
// Kernel 3: per-row FFT -> filter + modReLU -> IFFT (real part)
//   FFT-768 = 3 x Stockham radix-2 FFT-256 (384 thr = 3 chunks x 128
//   butterflies) + twiddled DFT-3 combine.
//   Input to fft768 must be in chunk layout: elem q of chunk r = seq[3q+r].
//   Output is natural order.
// =====================================================================

__device__ __forceinline__ void fft768(
    float* __restrict__ Xr, float* __restrict__ Xi,     // in (chunk layout) + scratch
    float* __restrict__ Yr, float* __restrict__ Yi,     // out (natural order)
    const float* __restrict__ t256r, const float* __restrict__ t256i,
    const float* __restrict__ t768r, const float* __restrict__ t768i,
    int tid)
{
    const int c    = tid >> 7;      // chunk 0..2
    const int idx  = tid & 127;     // butterfly id within chunk
    const int base = c << 8;

#pragma unroll
    for (int st = 0; st < 8; st++) {
        float *sr, *si, *dr, *di;
        if ((st & 1) == 0) { sr = Xr; si = Xi; dr = Yr; di = Yi; }
        else               { sr = Yr; si = Yi; dr = Xr; di = Xi; }
        int s  = 1 << st;
        int q  = idx & (s - 1);
        int j  = idx - q;            // = s * (idx>>st): twiddle index (w_256^j)
        int i0 = base + idx;         // contiguous reads
        int i1 = i0 + 128;
        float ar = sr[i0], ai = si[i0];
        float br = sr[i1], bi = si[i1];
        float wr = t256r[j], wi = t256i[j];
        int o0 = base + idx + j;     // = base + q + 2*s*p
        float mr = ar - br, mi = ai - bi;
        dr[o0]     = ar + br;
        di[o0]     = ai + bi;
        dr[o0 + s] = mr * wr - mi * wi;
        di[o0 + s] = mr * wi + mi * wr;
        __syncthreads();
    }
    // 8 stages => result back in X (chunk-major sub-FFT results, natural within chunk)
    if (tid < 256) {
        int s = tid;
        float y0r = Xr[s],       y0i = Xi[s];
        float y1r = Xr[256 + s], y1i = Xi[256 + s];
        float y2r = Xr[512 + s], y2i = Xi[512 + s];
        float c1 = t768r[s], s1 = t768i[s];             // w = e^{-2pi i s/768}
        float c2 = c1 * c1 - s1 * s1;                   // w^2
        float s2 = 2.f * s1 * c1;
        float T1r = y1r * c1 - y1i * s1, T1i = y1r * s1 + y1i * c1;
        float T2r = y2r * c2 - y2i * s2, T2i = y2r * s2 + y2i * c2;
        float ur = T1r + T2r, ui = T1i + T2i;
        float vr = T1r - T2r, vi = T1i - T2i;
        const float K = 0.8660254037844386f;            // sqrt(3)/2
        Yr[s]       = y0r + ur;
        Yi[s]       = y0i + ui;
        float mrr = y0r - 0.5f * ur, mii = y0i - 0.5f * ui;
        Yr[256 + s] = mrr + K * vi;  Yi[256 + s] = mii - K * vr;
        Yr[512 + s] = mrr - K * vi;  Yi[512 + s] = mii + K * vr;
    }
    __syncthreads();
}

__global__ void __launch_bounds__(384)
k_main(const float* __restrict__ x, const float* __restrict__ Wb,
       const float* __restrict__ bias, float* __restrict__ out)
{
    __shared__ float Ar[768], Ai[768];
    __shared__ float Br[768], Bi[768];
    __shared__ float t256r[128], t256i[128];
    __shared__ float t768r[256], t768i[256];

    const int tid = threadIdx.x;
    const int n   = blockIdx.x & (NDIM - 1);
    const int b   = blockIdx.x >> 12;       // 0..7

    // twiddle tables
    if (tid < 128) {
        float s, c;
        sincosf(-6.283185307179586f * (float)tid / 256.0f, &s, &c);
        t256r[tid] = c; t256i[tid] = s;
    } else {
        int u = tid - 128;                  // 0..255
        float s, c;
        sincosf(-6.283185307179586f * (float)u / 768.0f, &s, &c);
        t768r[u] = c; t768i[u] = s;
    }

    // load one real row into chunk layout: elem q of chunk r = x[3q+r]
    const float* xp = x + ((size_t)b * NDIM + n) * DDIM;
#pragma unroll
    for (int j = tid; j < 768; j += 384) {
        int q3 = j / 3;
        int r3 = j - 3 * q3;
        Ar[r3 * 256 + q3] = xp[j];
        Ai[r3 * 256 + q3] = 0.0f;
    }
    __syncthreads();

    // forward FFT: Z -> B (natural order)
    fft768(Ar, Ai, Br, Bi, t256r, t256i, t768r, t768i, tid);

    // pointwise, full spectrum (no symmetry assumptions):
    //   G = Z * W;  modReLU;  store conj(G) in chunk layout -> A
    const float* wbp = Wb + (size_t)n * DDIM;
    const float* dp  = g_delta + b * DDIM;
#pragma unroll
    for (int k = tid; k < 768; k += 384) {
        float w  = wbp[k] + dp[k];
        float gr = Br[k] * w;
        float gi = Bi[k] * w;
        float mag = sqrtf(gr * gr + gi * gi);
        float sc  = fmaxf(mag + bias[k], 0.0f) / fmaxf(mag, 1e-8f);
        gr *= sc; gi *= sc;
        int q3 = k / 3;
        int r3 = k - 3 * q3;
        Ar[r3 * 256 + q3] = gr;
        Ai[r3 * 256 + q3] = -gi;        // conj for inverse-via-forward trick
    }
    __syncthreads();

    // inverse: ifft(G) = conj(FFT(conj G))/768 ; y = Re = Re(FFT(conjG))/768
    fft768(Ar, Ai, Br, Bi, t256r, t256i, t768r, t768i, tid);

    const float inv = 1.0f / 768.0f;
    float* op = out + ((size_t)b * NDIM + n) * DDIM;
#pragma unroll
    for (int j = tid; j < 768; j += 384) {
        op[j] = Br[j] * inv;
    }
}

// =====================================================================
extern "C" void kernel_launch(void* const* d_in, const int* in_sizes, int n_in,
                              void* d_out, int out_size) {
    const float* x    = (const float*)d_in[0];
    const float* Wb   = (const float*)d_in[1];
    const float* bias = (const float*)d_in[2];
    const float* w1   = (const float*)d_in[3];
    const float* b1   = (const float*)d_in[4];
    const float* w2   = (const float*)d_in[5];
    const float* b2   = (const float*)d_in[6];
    float* out = (float*)d_out;

    dim3 gmean(NCHUNK, BDIM);
    k_mean_part<<<gmean, DDIM>>>(x);
    k_mean_fin<<<BDIM, DDIM>>>();
    k_mlp<<<BDIM, DDIM>>>(w1, b1, w2, b2);
    k_main<<<BDIM * NDIM, 384>>>(x, Wb, bias, out);
}

// round 13
// speedup vs baseline: 1.5199x; 1.5199x over previous
#include <cuda_runtime.h>
#include <math.h>

#define BDIM 8
#define NDIM 4096
#define DDIM 768
#define HDIM 256
#define NCHUNK 256
#define ROWS_PER_CHUNK (NDIM / NCHUNK)   // 16

// ---- scratch (no cudaMalloc allowed) ----
__device__ float  g_partial[BDIM * NCHUNK * DDIM];
__device__ float  g_delta[BDIM * DDIM];
__device__ float2 g_t256[64];
__device__ float2 g_t768[256];

// smem bank swizzle: bijection on [0,768), XOR low 4 idx bits with bits [4:8)
#define SIDX(e) ((e) ^ (((e) >> 4) & 15))

__device__ __forceinline__ float2 cmul(float2 a, float2 b) {
    return make_float2(a.x * b.x - a.y * b.y, a.x * b.y + a.y * b.x);
}
__device__ __forceinline__ float2 cadd(float2 a, float2 b) { return make_float2(a.x + b.x, a.y + b.y); }
__device__ __forceinline__ float2 csub(float2 a, float2 b) { return make_float2(a.x - b.x, a.y - b.y); }

// =====================================================================
// Twiddle init (rerun every call; deterministic)
// =====================================================================
__global__ void k_twiddle() {
    int t = threadIdx.x;
    if (t < 64) {
        float s, c;
        sincosf(-6.283185307179586f * (float)t / 256.0f, &s, &c);
        g_t256[t] = make_float2(c, s);
    }
    int u = t - 64;
    if (u >= 0 && u < 256) {
        float s, c;
        sincosf(-6.283185307179586f * (float)u / 768.0f, &s, &c);
        g_t768[u] = make_float2(c, s);
    }
}

// =====================================================================
// Mean partials: grid (NCHUNK, B), block DDIM
// =====================================================================
__global__ void k_mean_part(const float* __restrict__ x) {
    int chunk = blockIdx.x;
    int b = blockIdx.y;
    int d = threadIdx.x;
    const float* p = x + ((size_t)b * NDIM + (size_t)chunk * ROWS_PER_CHUNK) * DDIM + d;
    float acc = 0.f;
#pragma unroll
    for (int i = 0; i < ROWS_PER_CHUNK; i++) acc += p[(size_t)i * DDIM];
    g_partial[((size_t)b * NCHUNK + chunk) * DDIM + d] = acc;
}

// =====================================================================
// Fused mean-finalize + MLP: grid B, block DDIM (768)
// =====================================================================
__global__ void k_fin_mlp(const float* __restrict__ w1, const float* __restrict__ b1,
                          const float* __restrict__ w2, const float* __restrict__ b2) {
    __shared__ float cs[DDIM];
    __shared__ float hp[3 * HDIM];
    __shared__ float hs[HDIM];
    int b = blockIdx.x;
    int t = threadIdx.x;
    float acc = 0.f;
#pragma unroll 8
    for (int ch = 0; ch < NCHUNK; ch++)
        acc += g_partial[((size_t)b * NCHUNK + ch) * DDIM + t];
    cs[t] = acc * (1.0f / NDIM);
    __syncthreads();
    // split 768->256 GEMV across 3 thread-groups
    int g = t >> 8, r = t & 255;
    int k0 = g * 256;
    float a = 0.f;
#pragma unroll 8
    for (int k = 0; k < 256; k++) a = fmaf(cs[k0 + k], w1[(k0 + k) * HDIM + r], a);
    hp[g * HDIM + r] = a;
    __syncthreads();
    if (t < HDIM) {
        float s = hp[t] + hp[HDIM + t] + hp[2 * HDIM + t] + b1[t];
        float x3 = s * s * s;
        hs[t] = 0.5f * s * (1.0f + tanhf(0.7978845608028654f * (s + 0.044715f * x3)));
    }
    __syncthreads();
    float o = b2[t];
#pragma unroll 8
    for (int k = 0; k < HDIM; k++) o = fmaf(hs[k], w2[k * DDIM + t], o);
    g_delta[b * DDIM + t] = o;
}

// =====================================================================
// FFT-768 = 3 x (256-pt Stockham radix-4, 4 stages) + twiddled DFT-3.
// Input in arg-X (chunk layout, swizzled), output natural order in arg-Y.
// 192 threads: 3 chunks x 64 radix-4 butterflies.
// =====================================================================
__device__ __forceinline__ void fft768_r4(
    float2* __restrict__ X, float2* __restrict__ Y,
    const float2* __restrict__ t256, const float2* __restrict__ t768, int tid)
{
    const int ch   = tid >> 6;       // chunk 0..2
    const int idx  = tid & 63;
    const int base = ch << 8;

#pragma unroll
    for (int st = 0; st < 4; st++) {
        float2* src = (st & 1) ? Y : X;
        float2* dst = (st & 1) ? X : Y;
        int s = 1 << (2 * st);           // 1,4,16,64
        int q = idx & (s - 1);
        int j = idx - q;                 // s*P, twiddle exponent (W_256^j)
        float2 a = src[SIDX(base + idx)];
        float2 b = src[SIDX(base + idx + 64)];
        float2 c = src[SIDX(base + idx + 128)];
        float2 d = src[SIDX(base + idx + 192)];
        float2 apc = cadd(a, c), amc = csub(a, c);
        float2 bpd = cadd(b, d), bmd = csub(b, d);
        float2 e1 = make_float2(amc.x + bmd.y, amc.y - bmd.x);   // (a-c) - i(b-d)
        float2 e2 = csub(apc, bpd);
        float2 e3 = make_float2(amc.x - bmd.y, amc.y + bmd.x);   // (a-c) + i(b-d)
        int o = base + q + 4 * j;
        if (st < 3) {
            float2 w1 = t256[j];
            float2 w2 = cmul(w1, w1);
            float2 w3 = cmul(w2, w1);
            dst[SIDX(o)]         = cadd(apc, bpd);
            dst[SIDX(o + s)]     = cmul(e1, w1);
            dst[SIDX(o + 2 * s)] = cmul(e2, w2);
            dst[SIDX(o + 3 * s)] = cmul(e3, w3);
        } else {                         // s=64: all twiddles = 1
            dst[SIDX(o)]       = cadd(apc, bpd);
            dst[SIDX(o + 64)]  = e1;
            dst[SIDX(o + 128)] = e2;
            dst[SIDX(o + 192)] = e3;
        }
        __syncthreads();
    }
    // sub-FFT results in X (chunk-major). DFT-3 combine -> Y natural order.
    for (int s5 = tid; s5 < 256; s5 += 192) {
        float2 y0 = X[SIDX(s5)];
        float2 y1 = X[SIDX(256 + s5)];
        float2 y2 = X[SIDX(512 + s5)];
        float2 w  = t768[s5];
        float2 w2 = cmul(w, w);
        float2 T1 = cmul(y1, w);
        float2 T2 = cmul(y2, w2);
        float2 u = cadd(T1, T2);
        float2 v = csub(T1, T2);
        const float K = 0.8660254037844386f;   // sqrt(3)/2
        Y[SIDX(s5)] = cadd(y0, u);
        float mr = y0.x - 0.5f * u.x, mi = y0.y - 0.5f * u.y;
        Y[SIDX(256 + s5)] = make_float2(mr + K * v.y, mi - K * v.x);
        Y[SIDX(512 + s5)] = make_float2(mr - K * v.y, mi + K * v.x);
    }
    __syncthreads();
}

// =====================================================================
// Main per-row kernel: FFT -> filter + modReLU -> IFFT (real part)
// =====================================================================
__global__ void __launch_bounds__(192)
k_main(const float* __restrict__ x, const float* __restrict__ Wb,
       const float* __restrict__ bias, float* __restrict__ out)
{
    __shared__ __align__(16) float2 A[768];
    __shared__ __align__(16) float2 B[768];
    __shared__ float2 t256[64];
    __shared__ float2 t768[256];

    const int tid = threadIdx.x;
    const int n   = blockIdx.x & (NDIM - 1);
    const int b   = blockIdx.x >> 12;

    // twiddles from global (precomputed)
    if (tid < 64) t256[tid] = g_t256[tid];
    for (int u = tid; u < 256; u += 192) t768[u] = g_t768[u];

    // load row (float4), scatter into chunk layout: elem q of chunk r = x[3q+r]
    const float4* xp4 = (const float4*)(x + ((size_t)b * NDIM + n) * DDIM);
    float4 v = xp4[tid];
    {
        int j0 = 4 * tid;
        float vv[4] = {v.x, v.y, v.z, v.w};
#pragma unroll
        for (int r = 0; r < 4; r++) {
            int j  = j0 + r;
            int q3 = j / 3;
            int r3 = j - 3 * q3;
            A[SIDX(r3 * 256 + q3)] = make_float2(vv[r], 0.f);
        }
    }
    __syncthreads();

    fft768_r4(A, B, t256, t768, tid);      // spectrum Z natural in B

    // pointwise: G = Z*W, modReLU, store conj(G) back in chunk layout -> A
    const float* wbp = Wb + (size_t)n * DDIM;
    const float* dp  = g_delta + b * DDIM;
    for (int k = tid; k < 768; k += 192) {
        float w = wbp[k] + dp[k];
        float2 z = B[SIDX(k)];
        float gr = z.x * w, gi = z.y * w;
        float mag = sqrtf(gr * gr + gi * gi);
        float sc  = fmaxf(mag + bias[k], 0.f) / fmaxf(mag, 1e-8f);
        gr *= sc; gi *= sc;
        int q3 = k / 3;
        int r3 = k - 3 * q3;
        A[SIDX(r3 * 256 + q3)] = make_float2(gr, -gi);   // conj for ifft-via-fft
    }
    __syncthreads();

    fft768_r4(A, B, t256, t768, tid);      // q = FFT(conj G) natural in B

    // y = Re(ifft(G)) = Re(q)/768
    const float inv = 1.0f / 768.0f;
    float4* op4 = (float4*)(out + ((size_t)b * NDIM + n) * DDIM);
    {
        int j0 = 4 * tid;
        float4 o;
        o.x = B[SIDX(j0 + 0)].x * inv;
        o.y = B[SIDX(j0 + 1)].x * inv;
        o.z = B[SIDX(j0 + 2)].x * inv;
        o.w = B[SIDX(j0 + 3)].x * inv;
        op4[tid] = o;
    }
}

// =====================================================================
extern "C" void kernel_launch(void* const* d_in, const int* in_sizes, int n_in,
                              void* d_out, int out_size) {
    const float* x    = (const float*)d_in[0];
    const float* Wb   = (const float*)d_in[1];
    const float* bias = (const float*)d_in[2];
    const float* w1   = (const float*)d_in[3];
    const float* b1   = (const float*)d_in[4];
    const float* w2   = (const float*)d_in[5];
    const float* b2   = (const float*)d_in[6];
    float* out = (float*)d_out;

    k_twiddle<<<1, 320>>>();
    dim3 gmean(NCHUNK, BDIM);
    k_mean_part<<<gmean, DDIM>>>(x);
    k_fin_mlp<<<BDIM, DDIM>>>(w1, b1, w2, b2);
    k_main<<<BDIM * NDIM, 192>>>(x, Wb, bias, out);
}